// round 1
// baseline (speedup 1.0000x reference)
#include <cuda_runtime.h>
#include <math.h>

#define DM 1024
#define NH 16
#define HD 64
#define BB 2
#define TT 2048
#define MM (BB*TT)   // 4096 rows

// Scratch (device globals; allocation inside kernel_launch is forbidden)
__device__ float g_q[MM*DM];
__device__ float g_k[MM*DM];
__device__ float g_v[MM*DM];
__device__ float g_a[MM*DM];

// ---------------------------------------------------------------------------
// GEMM: Y[M,DM] = X[M,DM] @ W^T + bias    (W is [DM,DM] row-major, torch Linear)
// Tiles: 128x128x16, 256 threads, 8x8 microtile per thread.
// ---------------------------------------------------------------------------
#define GBM 128
#define GBN 128
#define GBK 16

__global__ __launch_bounds__(256) void gemm_bias_kernel(
    const float* __restrict__ X, const float* __restrict__ W,
    const float* __restrict__ bias, float* __restrict__ Y)
{
    __shared__ float As[GBK][GBM];
    __shared__ float Bs[GBK][GBN];

    const int bm = blockIdx.y * GBM;
    const int bn = blockIdx.x * GBN;
    const int tid = threadIdx.x;
    const int tx = tid & 15;
    const int ty = tid >> 4;

    // loader: each thread loads 8 contiguous k for one row (two float4)
    const int lr = tid >> 1;            // 0..127
    const int lc = (tid & 1) * 8;       // 0 or 8

    const float* Xp = X + (size_t)(bm + lr) * DM + lc;
    const float* Wp = W + (size_t)(bn + lr) * DM + lc;

    float acc[8][8];
#pragma unroll
    for (int i = 0; i < 8; i++)
#pragma unroll
        for (int j = 0; j < 8; j++) acc[i][j] = 0.f;

    for (int k0 = 0; k0 < DM; k0 += GBK) {
        float4 a0 = *(const float4*)(Xp + k0);
        float4 a1 = *(const float4*)(Xp + k0 + 4);
        float4 b0 = *(const float4*)(Wp + k0);
        float4 b1 = *(const float4*)(Wp + k0 + 4);
        __syncthreads();
        As[lc + 0][lr] = a0.x; As[lc + 1][lr] = a0.y;
        As[lc + 2][lr] = a0.z; As[lc + 3][lr] = a0.w;
        As[lc + 4][lr] = a1.x; As[lc + 5][lr] = a1.y;
        As[lc + 6][lr] = a1.z; As[lc + 7][lr] = a1.w;
        Bs[lc + 0][lr] = b0.x; Bs[lc + 1][lr] = b0.y;
        Bs[lc + 2][lr] = b0.z; Bs[lc + 3][lr] = b0.w;
        Bs[lc + 4][lr] = b1.x; Bs[lc + 5][lr] = b1.y;
        Bs[lc + 6][lr] = b1.z; Bs[lc + 7][lr] = b1.w;
        __syncthreads();
#pragma unroll
        for (int k = 0; k < GBK; k++) {
            float a[8], b[8];
            *(float4*)(a)     = *(const float4*)&As[k][ty * 8];
            *(float4*)(a + 4) = *(const float4*)&As[k][ty * 8 + 4];
            *(float4*)(b)     = *(const float4*)&Bs[k][tx * 8];
            *(float4*)(b + 4) = *(const float4*)&Bs[k][tx * 8 + 4];
#pragma unroll
            for (int i = 0; i < 8; i++)
#pragma unroll
                for (int j = 0; j < 8; j++)
                    acc[i][j] += a[i] * b[j];
        }
    }

#pragma unroll
    for (int i = 0; i < 8; i++) {
        const int row = bm + ty * 8 + i;
#pragma unroll
        for (int j = 0; j < 8; j++) {
            const int col = bn + tx * 8 + j;
            Y[(size_t)row * DM + col] = acc[i][j] + bias[col];
        }
    }
}

// ---------------------------------------------------------------------------
// RoPE in-place on q and k. One thread per (b,t,h,d<32) rotation pair.
// ---------------------------------------------------------------------------
__global__ void rope_kernel(float* __restrict__ q, float* __restrict__ k)
{
    const int gid = blockIdx.x * blockDim.x + threadIdx.x;  // < MM*NH*32
    const int d = gid & 31;
    const int h = (gid >> 5) & (NH - 1);
    const int mt = gid >> 9;            // b*T + t,  0..4095
    const int t = mt & (TT - 1);

    // inv_freq = 10000^{-d/32} = exp(-ln(10000)/32 * d)
    const float inv = expf(-0.2878231366242558f * (float)d);
    const float ang = (float)t * inv;
    const float c = cosf(ang);
    const float s = sinf(ang);

    const size_t base = (size_t)mt * DM + h * HD + d;
    float q1 = q[base], q2 = q[base + 32];
    q[base]      = q1 * c - q2 * s;
    q[base + 32] = q2 * c + q1 * s;
    float k1 = k[base], k2 = k[base + 32];
    k[base]      = k1 * c - k2 * s;
    k[base + 32] = k2 * c + k1 * s;
}

// ---------------------------------------------------------------------------
// Flash attention fp32.  grid = (T/64, B*H), block = (16,16).
// Br = Bc = 64, hd = 64. Online softmax; P staged through smem for PV GEMM.
// Dynamic smem: Qs,Ks (transposed [d][r]), Vs [c][d], Ps [c][r]  = 64 KB.
// ---------------------------------------------------------------------------
#define FLASH_SMEM (4 * 64 * 64 * 4)

__global__ __launch_bounds__(256) void flash_kernel(
    const float* __restrict__ Q, const float* __restrict__ K,
    const float* __restrict__ V, float* __restrict__ O)
{
    extern __shared__ float sm[];
    float* Qs = sm;            // [d*64 + r]
    float* Ks = sm + 4096;     // [d*64 + c]
    float* Vs = sm + 8192;     // [c*64 + d]
    float* Ps = sm + 12288;    // [c*64 + r]

    const int tx = threadIdx.x, ty = threadIdx.y;
    const int tid = ty * 16 + tx;
    const int bh = blockIdx.y;                // b*NH + h
    const int r0 = blockIdx.x * 64;
    const int row_base = (bh >> 4) * TT;      // b*T
    const int col_off = (bh & (NH - 1)) * HD; // h*64

    const int lr = tid >> 2;        // 0..63
    const int ld = (tid & 3) * 16;  // 0,16,32,48

    // Q tile -> Qs transposed
    {
        const float* src = Q + (size_t)(row_base + r0 + lr) * DM + col_off + ld;
#pragma unroll
        for (int u = 0; u < 16; u += 4) {
            float4 v4 = *(const float4*)(src + u);
            Qs[(ld + u + 0) * 64 + lr] = v4.x;
            Qs[(ld + u + 1) * 64 + lr] = v4.y;
            Qs[(ld + u + 2) * 64 + lr] = v4.z;
            Qs[(ld + u + 3) * 64 + lr] = v4.w;
        }
    }

    float m[4], l[4], o[4][4];
#pragma unroll
    for (int i = 0; i < 4; i++) {
        m[i] = -1e30f; l[i] = 0.f;
#pragma unroll
        for (int j = 0; j < 4; j++) o[i][j] = 0.f;
    }
    const float scale = 0.125f;  // 64^-0.5

    for (int c0 = 0; c0 < TT; c0 += 64) {
        __syncthreads();   // protect Ks/Vs/Ps from previous iteration readers
        {
            const float* ks = K + (size_t)(row_base + c0 + lr) * DM + col_off + ld;
            const float* vs = V + (size_t)(row_base + c0 + lr) * DM + col_off + ld;
#pragma unroll
            for (int u = 0; u < 16; u += 4) {
                float4 kv = *(const float4*)(ks + u);
                Ks[(ld + u + 0) * 64 + lr] = kv.x;
                Ks[(ld + u + 1) * 64 + lr] = kv.y;
                Ks[(ld + u + 2) * 64 + lr] = kv.z;
                Ks[(ld + u + 3) * 64 + lr] = kv.w;
                *(float4*)&Vs[lr * 64 + ld + u] = *(const float4*)(vs + u);
            }
        }
        __syncthreads();

        // S = scale * Q K^T  (4x4 per thread)
        float s[4][4];
#pragma unroll
        for (int i = 0; i < 4; i++)
#pragma unroll
            for (int j = 0; j < 4; j++) s[i][j] = 0.f;
#pragma unroll
        for (int d = 0; d < 64; d++) {
            float a[4], b[4];
            *(float4*)a = *(const float4*)&Qs[d * 64 + ty * 4];
            *(float4*)b = *(const float4*)&Ks[d * 64 + tx * 4];
#pragma unroll
            for (int i = 0; i < 4; i++)
#pragma unroll
                for (int j = 0; j < 4; j++) s[i][j] += a[i] * b[j];
        }

        // online softmax per row (reduce over tx = lane bits 0..3)
#pragma unroll
        for (int i = 0; i < 4; i++) {
#pragma unroll
            for (int j = 0; j < 4; j++) s[i][j] *= scale;
            float mloc = fmaxf(fmaxf(s[i][0], s[i][1]), fmaxf(s[i][2], s[i][3]));
#pragma unroll
            for (int sh = 8; sh; sh >>= 1)
                mloc = fmaxf(mloc, __shfl_xor_sync(0xffffffffu, mloc, sh));
            const float mnew = fmaxf(m[i], mloc);
            const float alpha = expf(m[i] - mnew);
            float p[4], psum = 0.f;
#pragma unroll
            for (int j = 0; j < 4; j++) { p[j] = expf(s[i][j] - mnew); psum += p[j]; }
#pragma unroll
            for (int sh = 8; sh; sh >>= 1)
                psum += __shfl_xor_sync(0xffffffffu, psum, sh);
            l[i] = l[i] * alpha + psum;
            m[i] = mnew;
#pragma unroll
            for (int j = 0; j < 4; j++) o[i][j] *= alpha;
            // store P transposed: Ps[c][r]
#pragma unroll
            for (int j = 0; j < 4; j++)
                Ps[(tx * 4 + j) * 64 + ty * 4 + i] = p[j];
        }
        __syncthreads();

        // O += P @ V
#pragma unroll
        for (int c = 0; c < 64; c++) {
            float p4[4], v4[4];
            *(float4*)p4 = *(const float4*)&Ps[c * 64 + ty * 4];
            *(float4*)v4 = *(const float4*)&Vs[c * 64 + tx * 4];
#pragma unroll
            for (int i = 0; i < 4; i++)
#pragma unroll
                for (int j = 0; j < 4; j++) o[i][j] += p4[i] * v4[j];
        }
    }

#pragma unroll
    for (int i = 0; i < 4; i++) {
        const float inv_l = 1.f / l[i];
        const int row = row_base + r0 + ty * 4 + i;
#pragma unroll
        for (int j = 0; j < 4; j++)
            O[(size_t)row * DM + col_off + tx * 4 + j] = o[i][j] * inv_l;
    }
}

// ---------------------------------------------------------------------------
extern "C" void kernel_launch(void* const* d_in, const int* in_sizes, int n_in,
                              void* d_out, int out_size)
{
    (void)in_sizes; (void)n_in; (void)out_size;
    const float* q_in = (const float*)d_in[0];
    const float* k_in = (const float*)d_in[1];
    const float* v_in = (const float*)d_in[2];
    const float* Wq   = (const float*)d_in[3];
    const float* bq   = (const float*)d_in[4];
    const float* Wk   = (const float*)d_in[5];
    const float* bk   = (const float*)d_in[6];
    const float* Wv   = (const float*)d_in[7];
    const float* bv   = (const float*)d_in[8];
    const float* Wo   = (const float*)d_in[9];
    const float* bo   = (const float*)d_in[10];
    float* out = (float*)d_out;

    float *gq, *gk, *gv, *ga;
    cudaGetSymbolAddress((void**)&gq, g_q);
    cudaGetSymbolAddress((void**)&gk, g_k);
    cudaGetSymbolAddress((void**)&gv, g_v);
    cudaGetSymbolAddress((void**)&ga, g_a);

    const dim3 ggrid(DM / GBN, MM / GBM);   // (8, 32)
    gemm_bias_kernel<<<ggrid, 256>>>(q_in, Wq, bq, gq);
    gemm_bias_kernel<<<ggrid, 256>>>(k_in, Wk, bk, gk);
    gemm_bias_kernel<<<ggrid, 256>>>(v_in, Wv, bv, gv);

    const int rope_threads = MM * NH * 32;  // 2,097,152
    rope_kernel<<<rope_threads / 256, 256>>>(gq, gk);

    cudaFuncSetAttribute(flash_kernel,
                         cudaFuncAttributeMaxDynamicSharedMemorySize, FLASH_SMEM);
    flash_kernel<<<dim3(TT / 64, BB * NH), dim3(16, 16), FLASH_SMEM>>>(gq, gk, gv, ga);

    gemm_bias_kernel<<<ggrid, 256>>>(ga, Wo, bo, out);
}

// round 3
// speedup vs baseline: 1.3061x; 1.3061x over previous
#include <cuda_runtime.h>
#include <cuda_bf16.h>
#include <math.h>
#include <stdint.h>

#define DM 1024
#define NH 16
#define HD 64
#define BB 2
#define TT 2048
#define MM (BB*TT)   // 4096 rows

// Scratch (device globals; allocation inside kernel_launch is forbidden)
__device__ float g_q[MM*DM];
__device__ float g_k[MM*DM];
__device__ float g_v[MM*DM];
__device__ float g_a[MM*DM];

// ===========================================================================
// helpers
// ===========================================================================
__device__ __forceinline__ uint32_t smem_u32(const void* p) {
    uint32_t a;
    asm("{ .reg .u64 t; cvta.to.shared.u64 t, %1; cvt.u32.u64 %0, t; }"
        : "=r"(a) : "l"(p));
    return a;
}

#define LDSM4(r, addr) \
    asm volatile("ldmatrix.sync.aligned.m8n8.x4.shared.b16 {%0,%1,%2,%3}, [%4];" \
        : "=r"((r)[0]), "=r"((r)[1]), "=r"((r)[2]), "=r"((r)[3]) : "r"(addr))

#define LDSM2(r, addr) \
    asm volatile("ldmatrix.sync.aligned.m8n8.x2.shared.b16 {%0,%1}, [%2];" \
        : "=r"((r)[0]), "=r"((r)[1]) : "r"(addr))

#define MMA_BF16(d, a, b) \
    asm volatile("mma.sync.aligned.m16n8k16.row.col.f32.bf16.bf16.f32 " \
        "{%0,%1,%2,%3}, {%4,%5,%6,%7}, {%8,%9}, {%0,%1,%2,%3};" \
        : "+f"((d)[0]), "+f"((d)[1]), "+f"((d)[2]), "+f"((d)[3]) \
        : "r"((a)[0]), "r"((a)[1]), "r"((a)[2]), "r"((a)[3]), \
          "r"((b)[0]), "r"((b)[1]))

// fp32x4 -> bf16 hi/lo split (packed pairs, low half = even col)
__device__ __forceinline__ void cvt_split(float4 v, uint32_t& h01, uint32_t& h23,
                                          uint32_t& l01, uint32_t& l23) {
    __nv_bfloat162 h0 = __floats2bfloat162_rn(v.x, v.y);
    __nv_bfloat162 h1 = __floats2bfloat162_rn(v.z, v.w);
    __nv_bfloat162 l0 = __floats2bfloat162_rn(v.x - __low2float(h0),
                                              v.y - __high2float(h0));
    __nv_bfloat162 l1 = __floats2bfloat162_rn(v.z - __low2float(h1),
                                              v.w - __high2float(h1));
    h01 = *reinterpret_cast<uint32_t*>(&h0);
    h23 = *reinterpret_cast<uint32_t*>(&h1);
    l01 = *reinterpret_cast<uint32_t*>(&l0);
    l23 = *reinterpret_cast<uint32_t*>(&l1);
}

// ===========================================================================
// GEMM via mma.sync bf16 split: Y[M,1024] = X @ W^T + bias
// CTA 128x128, K-tile 32, 8 warps (2M x 4N), warp tile 64x32.
// Smem rows padded to 40 bf16 (80B): 16B-aligned + conflict-free ldmatrix.
// ===========================================================================
#define AST 40                       // smem row stride (bf16 elements)
#define TILE_U32 (128 * (AST / 2))   // 2560 u32 per tile
#define STAGE_U32 (4 * TILE_U32)     // Ah Al Bh Bl
#define GEMM_SMEM (2 * STAGE_U32 * 4)  // 81920 B

__global__ __launch_bounds__(256) void gemm_mma_kernel(
    const float* __restrict__ X, const float* __restrict__ W,
    const float* __restrict__ bias, float* __restrict__ Y)
{
    extern __shared__ uint32_t sm[];
    const int tid = threadIdx.x, wid = tid >> 5, lane = tid & 31;
    const int bm = blockIdx.y * 128, bn = blockIdx.x * 128;
    const int wm = (wid & 1) * 64;       // warp M offset
    const int wn = (wid >> 1) * 32;      // warp N offset
    const int lrow = tid >> 1;           // 0..127
    const int lhalf = (tid & 1) * 16;    // 0 or 16
    const uint32_t smem_base = smem_u32(sm);

    const float* xp = X + (size_t)(bm + lrow) * DM + lhalf;
    const float* wp = W + (size_t)(bn + lrow) * DM + lhalf;

    float acc[4][4][4];
#pragma unroll
    for (int mf = 0; mf < 4; mf++)
#pragma unroll
        for (int nf = 0; nf < 4; nf++)
#pragma unroll
            for (int r = 0; r < 4; r++) acc[mf][nf][r] = 0.f;

    float4 xr[4], wr[4];
#pragma unroll
    for (int q = 0; q < 4; q++) {
        xr[q] = *(const float4*)(xp + q * 4);
        wr[q] = *(const float4*)(wp + q * 4);
    }

    for (int t = 0; t < DM / 32; t++) {
        const int buf = t & 1;
        uint32_t* Ah = sm + buf * STAGE_U32;
        uint32_t* Al = Ah + TILE_U32;
        uint32_t* Bh = Al + TILE_U32;
        uint32_t* Bl = Bh + TILE_U32;
        const uint32_t su = lrow * (AST / 2) + (lhalf >> 1);

#pragma unroll
        for (int q = 0; q < 4; q++) {
            uint32_t h01, h23, l01, l23;
            cvt_split(xr[q], h01, h23, l01, l23);
            *(uint2*)&Ah[su + q * 2] = make_uint2(h01, h23);
            *(uint2*)&Al[su + q * 2] = make_uint2(l01, l23);
            cvt_split(wr[q], h01, h23, l01, l23);
            *(uint2*)&Bh[su + q * 2] = make_uint2(h01, h23);
            *(uint2*)&Bl[su + q * 2] = make_uint2(l01, l23);
        }
        __syncthreads();

        if (t < DM / 32 - 1) {
#pragma unroll
            for (int q = 0; q < 4; q++) {
                xr[q] = *(const float4*)(xp + (t + 1) * 32 + q * 4);
                wr[q] = *(const float4*)(wp + (t + 1) * 32 + q * 4);
            }
        }

        const uint32_t sb = smem_base + buf * STAGE_U32 * 4;
#pragma unroll
        for (int ks = 0; ks < 2; ks++) {
            uint32_t ah[4][4], al[4][4], bh[4][2], bl[4][2];
            const int arow = wm + (lane & 15);
            const int acol = ks * 16 + ((lane >> 4) << 3);
#pragma unroll
            for (int mf = 0; mf < 4; mf++) {
                const uint32_t ad = sb + ((arow + mf * 16) * AST + acol) * 2;
                LDSM4(ah[mf], ad);
                LDSM4(al[mf], ad + TILE_U32 * 4);
            }
            const int brow = wn + (lane & 7);
            const int bcol = ks * 16 + ((lane >> 3) & 1) * 8;
#pragma unroll
            for (int nf = 0; nf < 4; nf++) {
                const uint32_t bd = sb + 2 * TILE_U32 * 4
                                  + ((brow + nf * 8) * AST + bcol) * 2;
                LDSM2(bh[nf], bd);
                LDSM2(bl[nf], bd + TILE_U32 * 4);
            }
#pragma unroll
            for (int mf = 0; mf < 4; mf++)
#pragma unroll
                for (int nf = 0; nf < 4; nf++) {
                    MMA_BF16(acc[mf][nf], ah[mf], bh[nf]);
                    MMA_BF16(acc[mf][nf], al[mf], bh[nf]);
                    MMA_BF16(acc[mf][nf], ah[mf], bl[nf]);
                }
        }
        __syncthreads();
    }

    // epilogue: c frag: rows t/4, t/4+8 ; cols (t%4)*2, +1
#pragma unroll
    for (int mf = 0; mf < 4; mf++) {
        const int r0 = bm + wm + mf * 16 + (lane >> 2);
#pragma unroll
        for (int nf = 0; nf < 4; nf++) {
            const int c = bn + wn + nf * 8 + (lane & 3) * 2;
            const float b0 = bias[c], b1 = bias[c + 1];
            float2 v0 = make_float2(acc[mf][nf][0] + b0, acc[mf][nf][1] + b1);
            float2 v1 = make_float2(acc[mf][nf][2] + b0, acc[mf][nf][3] + b1);
            *(float2*)&Y[(size_t)r0 * DM + c] = v0;
            *(float2*)&Y[(size_t)(r0 + 8) * DM + c] = v1;
        }
    }
}

// ---------------------------------------------------------------------------
// RoPE in-place on q and k. One thread per (b,t,h,d<32) rotation pair.
// ---------------------------------------------------------------------------
__global__ void rope_kernel(float* __restrict__ q, float* __restrict__ k)
{
    const int gid = blockIdx.x * blockDim.x + threadIdx.x;
    const int d = gid & 31;
    const int h = (gid >> 5) & (NH - 1);
    const int mt = gid >> 9;
    const int t = mt & (TT - 1);

    const float inv = expf(-0.2878231366242558f * (float)d);
    const float ang = (float)t * inv;
    const float c = cosf(ang);
    const float s = sinf(ang);

    const size_t base = (size_t)mt * DM + h * HD + d;
    float q1 = q[base], q2 = q[base + 32];
    q[base]      = q1 * c - q2 * s;
    q[base + 32] = q2 * c + q1 * s;
    float k1 = k[base], k2 = k[base + 32];
    k[base]      = k1 * c - k2 * s;
    k[base + 32] = k2 * c + k1 * s;
}

// ---------------------------------------------------------------------------
// Flash attention fp32.  grid = (T/64, B*H), block = (16,16).
// ---------------------------------------------------------------------------
#define FLASH_SMEM (4 * 64 * 64 * 4)

__global__ __launch_bounds__(256) void flash_kernel(
    const float* __restrict__ Q, const float* __restrict__ K,
    const float* __restrict__ V, float* __restrict__ O)
{
    extern __shared__ float smf[];
    float* Qs = smf;            // [d*64 + r]
    float* Ks = smf + 4096;     // [d*64 + c]
    float* Vs = smf + 8192;     // [c*64 + d]
    float* Ps = smf + 12288;    // [c*64 + r]

    const int tx = threadIdx.x, ty = threadIdx.y;
    const int tid = ty * 16 + tx;
    const int bh = blockIdx.y;
    const int r0 = blockIdx.x * 64;
    const int row_base = (bh >> 4) * TT;
    const int col_off = (bh & (NH - 1)) * HD;

    const int lr = tid >> 2;
    const int ld = (tid & 3) * 16;

    {
        const float* src = Q + (size_t)(row_base + r0 + lr) * DM + col_off + ld;
#pragma unroll
        for (int u = 0; u < 16; u += 4) {
            float4 v4 = *(const float4*)(src + u);
            Qs[(ld + u + 0) * 64 + lr] = v4.x;
            Qs[(ld + u + 1) * 64 + lr] = v4.y;
            Qs[(ld + u + 2) * 64 + lr] = v4.z;
            Qs[(ld + u + 3) * 64 + lr] = v4.w;
        }
    }

    float m[4], l[4], o[4][4];
#pragma unroll
    for (int i = 0; i < 4; i++) {
        m[i] = -1e30f; l[i] = 0.f;
#pragma unroll
        for (int j = 0; j < 4; j++) o[i][j] = 0.f;
    }
    const float scale = 0.125f;

    for (int c0 = 0; c0 < TT; c0 += 64) {
        __syncthreads();
        {
            const float* ks = K + (size_t)(row_base + c0 + lr) * DM + col_off + ld;
            const float* vs = V + (size_t)(row_base + c0 + lr) * DM + col_off + ld;
#pragma unroll
            for (int u = 0; u < 16; u += 4) {
                float4 kv = *(const float4*)(ks + u);
                Ks[(ld + u + 0) * 64 + lr] = kv.x;
                Ks[(ld + u + 1) * 64 + lr] = kv.y;
                Ks[(ld + u + 2) * 64 + lr] = kv.z;
                Ks[(ld + u + 3) * 64 + lr] = kv.w;
                *(float4*)&Vs[lr * 64 + ld + u] = *(const float4*)(vs + u);
            }
        }
        __syncthreads();

        float s[4][4];
#pragma unroll
        for (int i = 0; i < 4; i++)
#pragma unroll
            for (int j = 0; j < 4; j++) s[i][j] = 0.f;
#pragma unroll
        for (int d = 0; d < 64; d++) {
            float a[4], b[4];
            *(float4*)a = *(const float4*)&Qs[d * 64 + ty * 4];
            *(float4*)b = *(const float4*)&Ks[d * 64 + tx * 4];
#pragma unroll
            for (int i = 0; i < 4; i++)
#pragma unroll
                for (int j = 0; j < 4; j++) s[i][j] += a[i] * b[j];
        }

#pragma unroll
        for (int i = 0; i < 4; i++) {
#pragma unroll
            for (int j = 0; j < 4; j++) s[i][j] *= scale;
            float mloc = fmaxf(fmaxf(s[i][0], s[i][1]), fmaxf(s[i][2], s[i][3]));
#pragma unroll
            for (int sh = 8; sh; sh >>= 1)
                mloc = fmaxf(mloc, __shfl_xor_sync(0xffffffffu, mloc, sh));
            const float mnew = fmaxf(m[i], mloc);
            const float alpha = expf(m[i] - mnew);
            float p[4], psum = 0.f;
#pragma unroll
            for (int j = 0; j < 4; j++) { p[j] = expf(s[i][j] - mnew); psum += p[j]; }
#pragma unroll
            for (int sh = 8; sh; sh >>= 1)
                psum += __shfl_xor_sync(0xffffffffu, psum, sh);
            l[i] = l[i] * alpha + psum;
            m[i] = mnew;
#pragma unroll
            for (int j = 0; j < 4; j++) o[i][j] *= alpha;
#pragma unroll
            for (int j = 0; j < 4; j++)
                Ps[(tx * 4 + j) * 64 + ty * 4 + i] = p[j];
        }
        __syncthreads();

#pragma unroll
        for (int c = 0; c < 64; c++) {
            float p4[4], v4[4];
            *(float4*)p4 = *(const float4*)&Ps[c * 64 + ty * 4];
            *(float4*)v4 = *(const float4*)&Vs[c * 64 + tx * 4];
#pragma unroll
            for (int i = 0; i < 4; i++)
#pragma unroll
                for (int j = 0; j < 4; j++) o[i][j] += p4[i] * v4[j];
        }
    }

#pragma unroll
    for (int i = 0; i < 4; i++) {
        const float inv_l = 1.f / l[i];
        const int row = row_base + r0 + ty * 4 + i;
#pragma unroll
        for (int j = 0; j < 4; j++)
            O[(size_t)row * DM + col_off + tx * 4 + j] = o[i][j] * inv_l;
    }
}

// ---------------------------------------------------------------------------
extern "C" void kernel_launch(void* const* d_in, const int* in_sizes, int n_in,
                              void* d_out, int out_size)
{
    (void)in_sizes; (void)n_in; (void)out_size;
    const float* q_in = (const float*)d_in[0];
    const float* k_in = (const float*)d_in[1];
    const float* v_in = (const float*)d_in[2];
    const float* Wq   = (const float*)d_in[3];
    const float* bq   = (const float*)d_in[4];
    const float* Wk   = (const float*)d_in[5];
    const float* bk   = (const float*)d_in[6];
    const float* Wv   = (const float*)d_in[7];
    const float* bv   = (const float*)d_in[8];
    const float* Wo   = (const float*)d_in[9];
    const float* bo   = (const float*)d_in[10];
    float* out = (float*)d_out;

    float *gq, *gk, *gv, *ga;
    cudaGetSymbolAddress((void**)&gq, g_q);
    cudaGetSymbolAddress((void**)&gk, g_k);
    cudaGetSymbolAddress((void**)&gv, g_v);
    cudaGetSymbolAddress((void**)&ga, g_a);

    cudaFuncSetAttribute(gemm_mma_kernel,
                         cudaFuncAttributeMaxDynamicSharedMemorySize, GEMM_SMEM);
    cudaFuncSetAttribute(flash_kernel,
                         cudaFuncAttributeMaxDynamicSharedMemorySize, FLASH_SMEM);

    const dim3 ggrid(DM / 128, MM / 128);   // (8, 32)
    gemm_mma_kernel<<<ggrid, 256, GEMM_SMEM>>>(q_in, Wq, bq, gq);
    gemm_mma_kernel<<<ggrid, 256, GEMM_SMEM>>>(k_in, Wk, bk, gk);
    gemm_mma_kernel<<<ggrid, 256, GEMM_SMEM>>>(v_in, Wv, bv, gv);

    const int rope_threads = MM * NH * 32;
    rope_kernel<<<rope_threads / 256, 256>>>(gq, gk);

    flash_kernel<<<dim3(TT / 64, BB * NH), dim3(16, 16), FLASH_SMEM>>>(gq, gk, gv, ga);

    gemm_mma_kernel<<<ggrid, 256, GEMM_SMEM>>>(ga, Wo, bo, out);
}

// round 4
// speedup vs baseline: 3.6653x; 2.8062x over previous
#include <cuda_runtime.h>
#include <cuda_bf16.h>
#include <cuda_fp16.h>
#include <math.h>
#include <stdint.h>

#define DM 1024
#define NH 16
#define HD 64
#define BB 2
#define TT 2048
#define MM (BB*TT)   // 4096 rows

// Scratch (device globals; allocation inside kernel_launch is forbidden)
__device__ float g_q[MM*DM];
__device__ float g_k[MM*DM];
__device__ float g_v[MM*DM];
__device__ float g_a[MM*DM];
__device__ __half g_qh[MM*DM];
__device__ __half g_kh[MM*DM];
__device__ __half g_vt[BB*NH*HD*TT];   // [bh][d][t]

// ===========================================================================
// helpers
// ===========================================================================
__device__ __forceinline__ uint32_t smem_u32(const void* p) {
    uint32_t a;
    asm("{ .reg .u64 t; cvta.to.shared.u64 t, %1; cvt.u32.u64 %0, t; }"
        : "=r"(a) : "l"(p));
    return a;
}

#define LDSM4(r, addr) \
    asm volatile("ldmatrix.sync.aligned.m8n8.x4.shared.b16 {%0,%1,%2,%3}, [%4];" \
        : "=r"((r)[0]), "=r"((r)[1]), "=r"((r)[2]), "=r"((r)[3]) : "r"(addr))

#define LDSM2(r, addr) \
    asm volatile("ldmatrix.sync.aligned.m8n8.x2.shared.b16 {%0,%1}, [%2];" \
        : "=r"((r)[0]), "=r"((r)[1]) : "r"(addr))

#define MMA_BF16(d, a, b) \
    asm volatile("mma.sync.aligned.m16n8k16.row.col.f32.bf16.bf16.f32 " \
        "{%0,%1,%2,%3}, {%4,%5,%6,%7}, {%8,%9}, {%0,%1,%2,%3};" \
        : "+f"((d)[0]), "+f"((d)[1]), "+f"((d)[2]), "+f"((d)[3]) \
        : "r"((a)[0]), "r"((a)[1]), "r"((a)[2]), "r"((a)[3]), \
          "r"((b)[0]), "r"((b)[1]))

#define MMA_FP16(d, a, b) \
    asm volatile("mma.sync.aligned.m16n8k16.row.col.f32.f16.f16.f32 " \
        "{%0,%1,%2,%3}, {%4,%5,%6,%7}, {%8,%9}, {%0,%1,%2,%3};" \
        : "+f"((d)[0]), "+f"((d)[1]), "+f"((d)[2]), "+f"((d)[3]) \
        : "r"((a)[0]), "r"((a)[1]), "r"((a)[2]), "r"((a)[3]), \
          "r"((b)[0]), "r"((b)[1]))

#define CP16(dst, src) \
    asm volatile("cp.async.ca.shared.global [%0], [%1], 16;" :: "r"(dst), "l"(src))
#define CPCOMMIT() asm volatile("cp.async.commit_group;" ::: "memory")
#define CPWAIT1()  asm volatile("cp.async.wait_group 1;" ::: "memory")

// fp32x4 -> bf16 hi/lo split (packed pairs, low half = even col)
__device__ __forceinline__ void cvt_split(float4 v, uint32_t& h01, uint32_t& h23,
                                          uint32_t& l01, uint32_t& l23) {
    __nv_bfloat162 h0 = __floats2bfloat162_rn(v.x, v.y);
    __nv_bfloat162 h1 = __floats2bfloat162_rn(v.z, v.w);
    __nv_bfloat162 l0 = __floats2bfloat162_rn(v.x - __low2float(h0),
                                              v.y - __high2float(h0));
    __nv_bfloat162 l1 = __floats2bfloat162_rn(v.z - __low2float(h1),
                                              v.w - __high2float(h1));
    h01 = *reinterpret_cast<uint32_t*>(&h0);
    h23 = *reinterpret_cast<uint32_t*>(&h1);
    l01 = *reinterpret_cast<uint32_t*>(&l0);
    l23 = *reinterpret_cast<uint32_t*>(&l1);
}

// ===========================================================================
// GEMM via mma.sync bf16 split: Y[M,1024] = X @ W^T + bias  (unchanged R3)
// ===========================================================================
#define AST 40
#define TILE_U32 (128 * (AST / 2))
#define STAGE_U32 (4 * TILE_U32)
#define GEMM_SMEM (2 * STAGE_U32 * 4)

__global__ __launch_bounds__(256) void gemm_mma_kernel(
    const float* __restrict__ X, const float* __restrict__ W,
    const float* __restrict__ bias, float* __restrict__ Y)
{
    extern __shared__ uint32_t sm[];
    const int tid = threadIdx.x, wid = tid >> 5, lane = tid & 31;
    const int bm = blockIdx.y * 128, bn = blockIdx.x * 128;
    const int wm = (wid & 1) * 64;
    const int wn = (wid >> 1) * 32;
    const int lrow = tid >> 1;
    const int lhalf = (tid & 1) * 16;
    const uint32_t smem_base = smem_u32(sm);

    const float* xp = X + (size_t)(bm + lrow) * DM + lhalf;
    const float* wp = W + (size_t)(bn + lrow) * DM + lhalf;

    float acc[4][4][4];
#pragma unroll
    for (int mf = 0; mf < 4; mf++)
#pragma unroll
        for (int nf = 0; nf < 4; nf++)
#pragma unroll
            for (int r = 0; r < 4; r++) acc[mf][nf][r] = 0.f;

    float4 xr[4], wr[4];
#pragma unroll
    for (int q = 0; q < 4; q++) {
        xr[q] = *(const float4*)(xp + q * 4);
        wr[q] = *(const float4*)(wp + q * 4);
    }

    for (int t = 0; t < DM / 32; t++) {
        const int buf = t & 1;
        uint32_t* Ah = sm + buf * STAGE_U32;
        uint32_t* Al = Ah + TILE_U32;
        uint32_t* Bh = Al + TILE_U32;
        uint32_t* Bl = Bh + TILE_U32;
        const uint32_t su = lrow * (AST / 2) + (lhalf >> 1);

#pragma unroll
        for (int q = 0; q < 4; q++) {
            uint32_t h01, h23, l01, l23;
            cvt_split(xr[q], h01, h23, l01, l23);
            *(uint2*)&Ah[su + q * 2] = make_uint2(h01, h23);
            *(uint2*)&Al[su + q * 2] = make_uint2(l01, l23);
            cvt_split(wr[q], h01, h23, l01, l23);
            *(uint2*)&Bh[su + q * 2] = make_uint2(h01, h23);
            *(uint2*)&Bl[su + q * 2] = make_uint2(l01, l23);
        }
        __syncthreads();

        if (t < DM / 32 - 1) {
#pragma unroll
            for (int q = 0; q < 4; q++) {
                xr[q] = *(const float4*)(xp + (t + 1) * 32 + q * 4);
                wr[q] = *(const float4*)(wp + (t + 1) * 32 + q * 4);
            }
        }

        const uint32_t sb = smem_base + buf * STAGE_U32 * 4;
#pragma unroll
        for (int ks = 0; ks < 2; ks++) {
            uint32_t ah[4][4], al[4][4], bh[4][2], bl[4][2];
            const int arow = wm + (lane & 15);
            const int acol = ks * 16 + ((lane >> 4) << 3);
#pragma unroll
            for (int mf = 0; mf < 4; mf++) {
                const uint32_t ad = sb + ((arow + mf * 16) * AST + acol) * 2;
                LDSM4(ah[mf], ad);
                LDSM4(al[mf], ad + TILE_U32 * 4);
            }
            const int brow = wn + (lane & 7);
            const int bcol = ks * 16 + ((lane >> 3) & 1) * 8;
#pragma unroll
            for (int nf = 0; nf < 4; nf++) {
                const uint32_t bd = sb + 2 * TILE_U32 * 4
                                  + ((brow + nf * 8) * AST + bcol) * 2;
                LDSM2(bh[nf], bd);
                LDSM2(bl[nf], bd + TILE_U32 * 4);
            }
#pragma unroll
            for (int mf = 0; mf < 4; mf++)
#pragma unroll
                for (int nf = 0; nf < 4; nf++) {
                    MMA_BF16(acc[mf][nf], ah[mf], bh[nf]);
                    MMA_BF16(acc[mf][nf], al[mf], bh[nf]);
                    MMA_BF16(acc[mf][nf], ah[mf], bl[nf]);
                }
        }
        __syncthreads();
    }

#pragma unroll
    for (int mf = 0; mf < 4; mf++) {
        const int r0 = bm + wm + mf * 16 + (lane >> 2);
#pragma unroll
        for (int nf = 0; nf < 4; nf++) {
            const int c = bn + wn + nf * 8 + (lane & 3) * 2;
            const float b0 = bias[c], b1 = bias[c + 1];
            float2 v0 = make_float2(acc[mf][nf][0] + b0, acc[mf][nf][1] + b1);
            float2 v1 = make_float2(acc[mf][nf][2] + b0, acc[mf][nf][3] + b1);
            *(float2*)&Y[(size_t)r0 * DM + c] = v0;
            *(float2*)&Y[(size_t)(r0 + 8) * DM + c] = v1;
        }
    }
}

// ---------------------------------------------------------------------------
// RoPE + fp16 convert: g_q,g_k (fp32) -> g_qh (x0.125, fp16), g_kh (fp16)
// ---------------------------------------------------------------------------
__global__ void rope_half_kernel(const float* __restrict__ q,
                                 const float* __restrict__ k,
                                 __half* __restrict__ qh,
                                 __half* __restrict__ kh)
{
    const int gid = blockIdx.x * blockDim.x + threadIdx.x;
    const int d = gid & 31;
    const int h = (gid >> 5) & (NH - 1);
    const int mt = gid >> 9;
    const int t = mt & (TT - 1);

    const float inv = expf(-0.2878231366242558f * (float)d);
    const float ang = (float)t * inv;
    const float c = cosf(ang);
    const float s = sinf(ang);

    const size_t base = (size_t)mt * DM + h * HD + d;
    float q1 = q[base], q2 = q[base + 32];
    qh[base]      = __float2half(0.125f * (q1 * c - q2 * s));
    qh[base + 32] = __float2half(0.125f * (q2 * c + q1 * s));
    float k1 = k[base], k2 = k[base + 32];
    kh[base]      = __float2half(k1 * c - k2 * s);
    kh[base + 32] = __float2half(k2 * c + k1 * s);
}

// ---------------------------------------------------------------------------
// V transpose + fp16 convert: g_v [b*T+t][h*64+d] -> g_vt [bh][d][t]
// ---------------------------------------------------------------------------
#define FST 72

__global__ __launch_bounds__(256) void v_trans_kernel(
    const float* __restrict__ V, __half* __restrict__ Vt)
{
    __shared__ __half s[64 * FST];
    const int tid = threadIdx.x;
    const int bh = blockIdx.y;
    const int t0 = blockIdx.x * 64;
    const int b = bh >> 4, h = bh & 15;

    {
        const int trow = tid >> 2, dseg = (tid & 3) * 16;
        const float* src = V + ((size_t)(b * TT + t0 + trow)) * DM + h * HD + dseg;
#pragma unroll
        for (int q = 0; q < 4; q++) {
            float4 v4 = ((const float4*)src)[q];
            s[(dseg + q * 4 + 0) * FST + trow] = __float2half(v4.x);
            s[(dseg + q * 4 + 1) * FST + trow] = __float2half(v4.y);
            s[(dseg + q * 4 + 2) * FST + trow] = __float2half(v4.z);
            s[(dseg + q * 4 + 3) * FST + trow] = __float2half(v4.w);
        }
    }
    __syncthreads();
    {
        const int drow = tid >> 2, tseg = (tid & 3) * 16;
        uint4* dst = (uint4*)(Vt + ((size_t)(bh * HD + drow)) * TT + t0 + tseg);
        const uint4* ssrc = (const uint4*)(s + drow * FST + tseg);
        dst[0] = ssrc[0];
        dst[1] = ssrc[1];
    }
}

// ---------------------------------------------------------------------------
// Flash attention, fp16 mma.sync.  grid = (T/128, B*H), 256 threads.
// 8 warps x 16 q-rows. cp.async double-buffered K/V tiles (64 keys).
// S/P entirely in registers (acc-frag -> A-frag repack).
// ---------------------------------------------------------------------------
#define FLASH_SMEM ((128 * FST + 4 * 64 * FST) * 2)   // 55296 B

__global__ __launch_bounds__(256, 2) void flash_mma_kernel(
    const __half* __restrict__ Qh, const __half* __restrict__ Kh,
    const __half* __restrict__ Vt, float* __restrict__ O)
{
    extern __shared__ __half fsm[];
    __half* Qs = fsm;                       // 128 x FST
    __half* Ks = fsm + 128 * FST;           // 2 x (64 x FST)
    __half* Vs = Ks + 2 * 64 * FST;         // 2 x (64 x FST)

    const int tid = threadIdx.x, wid = tid >> 5, lane = tid & 31;
    const int bh = blockIdx.y;
    const int b = bh >> 4, h = bh & 15;
    const int r0 = blockIdx.x * 128;
    const size_t rowb = (size_t)(b * TT + r0);

    // Q tile -> smem
    {
        const int row = tid >> 1, off = (tid & 1) * 32;
        const uint4* src = (const uint4*)(Qh + (rowb + row) * DM + h * HD + off);
        uint4* dst = (uint4*)(Qs + row * FST + off);
        dst[0] = src[0]; dst[1] = src[1]; dst[2] = src[2]; dst[3] = src[3];
    }

    // cp.async source/dest for K/V tiles
    const int lrow = tid >> 2, lseg = (tid & 3) * 16;
    const __half* ksrc = Kh + ((size_t)(b * TT) + lrow) * DM + h * HD + lseg;
    const __half* vsrc = Vt + ((size_t)(bh * HD + lrow)) * TT + lseg;
    const uint32_t kdst = smem_u32(Ks + lrow * FST + lseg);
    const uint32_t vdst = smem_u32(Vs + lrow * FST + lseg);
    const uint32_t bufB = 64 * FST * 2;

    // ldmatrix bases
    const uint32_t aBase = smem_u32(Qs + (wid * 16 + (lane & 15)) * FST + (lane >> 4) * 8);
    const uint32_t kBase = smem_u32(Ks + (lane & 7) * FST + ((lane >> 3) & 1) * 8);
    const uint32_t vBase = smem_u32(Vs + (lane & 7) * FST + ((lane >> 3) & 1) * 8);

    float oacc[8][4];
#pragma unroll
    for (int j = 0; j < 8; j++)
#pragma unroll
        for (int r = 0; r < 4; r++) oacc[j][r] = 0.f;
    float m0 = -1e30f, m1 = -1e30f, l0 = 0.f, l1 = 0.f;

    // prologue: tile 0
    CP16(kdst, ksrc);               CP16(kdst + 16, (const char*)ksrc + 16);
    CP16(vdst, vsrc);               CP16(vdst + 16, (const char*)vsrc + 16);
    CPCOMMIT();

    for (int t = 0; t < TT / 64; t++) {
        const int buf = t & 1;
        if (t + 1 < TT / 64) {
            const int c1 = (t + 1) * 64;
            const uint32_t kb = kdst + (buf ^ 1) * bufB;
            const uint32_t vb = vdst + (buf ^ 1) * bufB;
            const __half* kp = ksrc + (size_t)c1 * DM;
            const __half* vp = vsrc + c1;
            CP16(kb, kp);  CP16(kb + 16, (const char*)kp + 16);
            CP16(vb, vp);  CP16(vb + 16, (const char*)vp + 16);
        }
        CPCOMMIT();
        CPWAIT1();
        __syncthreads();

        // ---- S = Qs @ Ks^T (scale pre-folded into Q) ----
        float sacc[8][4];
#pragma unroll
        for (int j = 0; j < 8; j++)
#pragma unroll
            for (int r = 0; r < 4; r++) sacc[j][r] = 0.f;

        const uint32_t kB = kBase + buf * bufB;
#pragma unroll
        for (int s = 0; s < 4; s++) {
            uint32_t a[4];
            LDSM4(a, aBase + s * 32);
#pragma unroll
            for (int j = 0; j < 8; j++) {
                uint32_t bk[2];
                LDSM2(bk, kB + s * 32 + j * (8 * FST * 2));
                MMA_FP16(sacc[j], a, bk);
            }
        }

        // ---- online softmax ----
        float mx0 = -1e30f, mx1 = -1e30f;
#pragma unroll
        for (int j = 0; j < 8; j++) {
            mx0 = fmaxf(mx0, fmaxf(sacc[j][0], sacc[j][1]));
            mx1 = fmaxf(mx1, fmaxf(sacc[j][2], sacc[j][3]));
        }
        mx0 = fmaxf(mx0, __shfl_xor_sync(0xffffffffu, mx0, 1));
        mx0 = fmaxf(mx0, __shfl_xor_sync(0xffffffffu, mx0, 2));
        mx1 = fmaxf(mx1, __shfl_xor_sync(0xffffffffu, mx1, 1));
        mx1 = fmaxf(mx1, __shfl_xor_sync(0xffffffffu, mx1, 2));

        const float mn0 = fmaxf(m0, mx0), mn1 = fmaxf(m1, mx1);
        const float al0 = __expf(m0 - mn0), al1 = __expf(m1 - mn1);
        m0 = mn0; m1 = mn1;

        float sum0 = 0.f, sum1 = 0.f;
        uint32_t P0[8], P1[8];
#pragma unroll
        for (int j = 0; j < 8; j++) {
            float p0 = __expf(sacc[j][0] - m0);
            float p1 = __expf(sacc[j][1] - m0);
            float p2 = __expf(sacc[j][2] - m1);
            float p3 = __expf(sacc[j][3] - m1);
            sum0 += p0 + p1;
            sum1 += p2 + p3;
            __half2 h0 = __floats2half2_rn(p0, p1);
            __half2 h1 = __floats2half2_rn(p2, p3);
            P0[j] = *reinterpret_cast<uint32_t*>(&h0);
            P1[j] = *reinterpret_cast<uint32_t*>(&h1);
        }
        sum0 += __shfl_xor_sync(0xffffffffu, sum0, 1);
        sum0 += __shfl_xor_sync(0xffffffffu, sum0, 2);
        sum1 += __shfl_xor_sync(0xffffffffu, sum1, 1);
        sum1 += __shfl_xor_sync(0xffffffffu, sum1, 2);
        l0 = l0 * al0 + sum0;
        l1 = l1 * al1 + sum1;

#pragma unroll
        for (int j = 0; j < 8; j++) {
            oacc[j][0] *= al0; oacc[j][1] *= al0;
            oacc[j][2] *= al1; oacc[j][3] *= al1;
        }

        // ---- O += P @ V  (A frags from P0/P1 regs) ----
        const uint32_t vB = vBase + buf * bufB;
#pragma unroll
        for (int s = 0; s < 4; s++) {
            uint32_t ap[4];
            ap[0] = P0[2 * s];     ap[1] = P1[2 * s];
            ap[2] = P0[2 * s + 1]; ap[3] = P1[2 * s + 1];
#pragma unroll
            for (int j = 0; j < 8; j++) {
                uint32_t bv[2];
                LDSM2(bv, vB + s * 32 + j * (8 * FST * 2));
                MMA_FP16(oacc[j], ap, bv);
            }
        }
        __syncthreads();
    }

    // epilogue
    const float inv0 = 1.f / l0, inv1 = 1.f / l1;
    const size_t orow = rowb + wid * 16 + (lane >> 2);
    float* op0 = O + orow * DM + h * HD + (lane & 3) * 2;
    float* op1 = op0 + 8 * DM;
#pragma unroll
    for (int j = 0; j < 8; j++) {
        *(float2*)(op0 + j * 8) = make_float2(oacc[j][0] * inv0, oacc[j][1] * inv0);
        *(float2*)(op1 + j * 8) = make_float2(oacc[j][2] * inv1, oacc[j][3] * inv1);
    }
}

// ---------------------------------------------------------------------------
extern "C" void kernel_launch(void* const* d_in, const int* in_sizes, int n_in,
                              void* d_out, int out_size)
{
    (void)in_sizes; (void)n_in; (void)out_size;
    const float* q_in = (const float*)d_in[0];
    const float* k_in = (const float*)d_in[1];
    const float* v_in = (const float*)d_in[2];
    const float* Wq   = (const float*)d_in[3];
    const float* bq   = (const float*)d_in[4];
    const float* Wk   = (const float*)d_in[5];
    const float* bk   = (const float*)d_in[6];
    const float* Wv   = (const float*)d_in[7];
    const float* bv   = (const float*)d_in[8];
    const float* Wo   = (const float*)d_in[9];
    const float* bo   = (const float*)d_in[10];
    float* out = (float*)d_out;

    float *gq, *gk, *gv, *ga;
    __half *gqh, *gkh, *gvt;
    cudaGetSymbolAddress((void**)&gq, g_q);
    cudaGetSymbolAddress((void**)&gk, g_k);
    cudaGetSymbolAddress((void**)&gv, g_v);
    cudaGetSymbolAddress((void**)&ga, g_a);
    cudaGetSymbolAddress((void**)&gqh, g_qh);
    cudaGetSymbolAddress((void**)&gkh, g_kh);
    cudaGetSymbolAddress((void**)&gvt, g_vt);

    cudaFuncSetAttribute(gemm_mma_kernel,
                         cudaFuncAttributeMaxDynamicSharedMemorySize, GEMM_SMEM);
    cudaFuncSetAttribute(flash_mma_kernel,
                         cudaFuncAttributeMaxDynamicSharedMemorySize, FLASH_SMEM);

    const dim3 ggrid(DM / 128, MM / 128);   // (8, 32)
    gemm_mma_kernel<<<ggrid, 256, GEMM_SMEM>>>(q_in, Wq, bq, gq);
    gemm_mma_kernel<<<ggrid, 256, GEMM_SMEM>>>(k_in, Wk, bk, gk);
    gemm_mma_kernel<<<ggrid, 256, GEMM_SMEM>>>(v_in, Wv, bv, gv);

    rope_half_kernel<<<(MM * NH * 32) / 256, 256>>>(gq, gk, gqh, gkh);
    v_trans_kernel<<<dim3(TT / 64, BB * NH), 256>>>(gv, gvt);

    flash_mma_kernel<<<dim3(TT / 128, BB * NH), 256, FLASH_SMEM>>>(gqh, gkh, gvt, ga);

    gemm_mma_kernel<<<ggrid, 256, GEMM_SMEM>>>(ga, Wo, bo, out);
}

// round 5
// speedup vs baseline: 4.7615x; 1.2991x over previous
#include <cuda_runtime.h>
#include <cuda_fp16.h>
#include <math.h>
#include <stdint.h>

#define DM 1024
#define NH 16
#define HD 64
#define BB 2
#define TT 2048
#define MM (BB*TT)   // 4096 rows

// Scratch (device globals; allocation inside kernel_launch is forbidden)
__device__ float g_q[MM*DM];
__device__ float g_k[MM*DM];
__device__ float g_v[MM*DM];
__device__ float g_a[MM*DM];
__device__ __half g_qh[MM*DM];
__device__ __half g_kh[MM*DM];
__device__ __half g_vt[BB*NH*HD*TT];   // [bh][d][t]

// ===========================================================================
// helpers
// ===========================================================================
__device__ __forceinline__ uint32_t smem_u32(const void* p) {
    uint32_t a;
    asm("{ .reg .u64 t; cvta.to.shared.u64 t, %1; cvt.u32.u64 %0, t; }"
        : "=r"(a) : "l"(p));
    return a;
}

#define LDSM4(r, addr) \
    asm volatile("ldmatrix.sync.aligned.m8n8.x4.shared.b16 {%0,%1,%2,%3}, [%4];" \
        : "=r"((r)[0]), "=r"((r)[1]), "=r"((r)[2]), "=r"((r)[3]) : "r"(addr))

#define MMA_FP16(d, a, b0, b1) \
    asm volatile("mma.sync.aligned.m16n8k16.row.col.f32.f16.f16.f32 " \
        "{%0,%1,%2,%3}, {%4,%5,%6,%7}, {%8,%9}, {%0,%1,%2,%3};" \
        : "+f"((d)[0]), "+f"((d)[1]), "+f"((d)[2]), "+f"((d)[3]) \
        : "r"((a)[0]), "r"((a)[1]), "r"((a)[2]), "r"((a)[3]), \
          "r"(b0), "r"(b1))

#define CP16(dst, src) \
    asm volatile("cp.async.ca.shared.global [%0], [%1], 16;" :: "r"(dst), "l"(src))
#define CPCOMMIT() asm volatile("cp.async.commit_group;" ::: "memory")
#define CPWAIT1()  asm volatile("cp.async.wait_group 1;" ::: "memory")

// fp32x4 -> fp16 hi + fp16 residual (packed pairs)
__device__ __forceinline__ void cvt_split16(float4 v, uint32_t& h01, uint32_t& h23,
                                            uint32_t& l01, uint32_t& l23) {
    __half2 h0 = __floats2half2_rn(v.x, v.y);
    __half2 h1 = __floats2half2_rn(v.z, v.w);
    __half2 l0 = __floats2half2_rn(v.x - __low2float(h0),
                                   v.y - __high2float(h0));
    __half2 l1 = __floats2half2_rn(v.z - __low2float(h1),
                                   v.w - __high2float(h1));
    h01 = *reinterpret_cast<uint32_t*>(&h0);
    h23 = *reinterpret_cast<uint32_t*>(&h1);
    l01 = *reinterpret_cast<uint32_t*>(&l0);
    l23 = *reinterpret_cast<uint32_t*>(&l1);
}
__device__ __forceinline__ void cvt_hi16(float4 v, uint32_t& h01, uint32_t& h23) {
    __half2 h0 = __floats2half2_rn(v.x, v.y);
    __half2 h1 = __floats2half2_rn(v.z, v.w);
    h01 = *reinterpret_cast<uint32_t*>(&h0);
    h23 = *reinterpret_cast<uint32_t*>(&h1);
}

// ===========================================================================
// GEMM via mma.sync fp16 2-term split: Y[M,1024] = X @ W^T + bias
// A = Ah + Al (fp16 hi + residual), B = Bh (fp16).  D = Ah*Bh + Al*Bh.
// CTA 128x128, K-tile 32, 8 warps (2M x 4N), warp tile 64x32.
// ===========================================================================
#define AST 40
#define TILE_U32 (128 * (AST / 2))     // 2560 u32
#define STAGE_U32 (3 * TILE_U32)       // Ah Al Bh
#define GEMM_SMEM (2 * STAGE_U32 * 4)  // 61440 B

__global__ __launch_bounds__(256) void gemm_mma_kernel(
    const float* __restrict__ X, const float* __restrict__ W,
    const float* __restrict__ bias, float* __restrict__ Y)
{
    extern __shared__ uint32_t sm[];
    const int tid = threadIdx.x, wid = tid >> 5, lane = tid & 31;
    const int bm = blockIdx.y * 128, bn = blockIdx.x * 128;
    const int wm = (wid & 1) * 64;
    const int wn = (wid >> 1) * 32;
    const int lrow = tid >> 1;
    const int lhalf = (tid & 1) * 16;
    const uint32_t smem_base = smem_u32(sm);

    const float* xp = X + (size_t)(bm + lrow) * DM + lhalf;
    const float* wp = W + (size_t)(bn + lrow) * DM + lhalf;

    float acc[4][4][4];
#pragma unroll
    for (int mf = 0; mf < 4; mf++)
#pragma unroll
        for (int nf = 0; nf < 4; nf++)
#pragma unroll
            for (int r = 0; r < 4; r++) acc[mf][nf][r] = 0.f;

    float4 xr[4], wr[4];
#pragma unroll
    for (int q = 0; q < 4; q++) {
        xr[q] = *(const float4*)(xp + q * 4);
        wr[q] = *(const float4*)(wp + q * 4);
    }

    for (int t = 0; t < DM / 32; t++) {
        const int buf = t & 1;
        uint32_t* Ah = sm + buf * STAGE_U32;
        uint32_t* Al = Ah + TILE_U32;
        uint32_t* Bh = Al + TILE_U32;
        const uint32_t su = lrow * (AST / 2) + (lhalf >> 1);

#pragma unroll
        for (int q = 0; q < 4; q++) {
            uint32_t h01, h23, l01, l23;
            cvt_split16(xr[q], h01, h23, l01, l23);
            *(uint2*)&Ah[su + q * 2] = make_uint2(h01, h23);
            *(uint2*)&Al[su + q * 2] = make_uint2(l01, l23);
            cvt_hi16(wr[q], h01, h23);
            *(uint2*)&Bh[su + q * 2] = make_uint2(h01, h23);
        }
        __syncthreads();

        if (t < DM / 32 - 1) {
#pragma unroll
            for (int q = 0; q < 4; q++) {
                xr[q] = *(const float4*)(xp + (t + 1) * 32 + q * 4);
                wr[q] = *(const float4*)(wp + (t + 1) * 32 + q * 4);
            }
        }

        const uint32_t sb = smem_base + buf * STAGE_U32 * 4;
#pragma unroll
        for (int ks = 0; ks < 2; ks++) {
            uint32_t ah[4][4], al[4][4], bh[2][4];
            const int arow = wm + (lane & 15);
            const int acol = ks * 16 + ((lane >> 4) << 3);
#pragma unroll
            for (int mf = 0; mf < 4; mf++) {
                const uint32_t ad = sb + ((arow + mf * 16) * AST + acol) * 2;
                LDSM4(ah[mf], ad);
                LDSM4(al[mf], ad + TILE_U32 * 4);
            }
            // B: ldmatrix.x4 loads two n-frags: lanes 0-15 -> n0-7 (k halves),
            // lanes 16-31 -> n8-15
            const int brow = wn + ((lane >> 4) << 3) + (lane & 7);
            const int bcol = ks * 16 + ((lane >> 3) & 1) * 8;
#pragma unroll
            for (int nf2 = 0; nf2 < 2; nf2++) {
                const uint32_t bd = sb + 2 * TILE_U32 * 4
                                  + ((brow + nf2 * 16) * AST + bcol) * 2;
                LDSM4(bh[nf2], bd);
            }
#pragma unroll
            for (int mf = 0; mf < 4; mf++)
#pragma unroll
                for (int nf = 0; nf < 4; nf++) {
                    const uint32_t b0 = bh[nf >> 1][(nf & 1) * 2];
                    const uint32_t b1 = bh[nf >> 1][(nf & 1) * 2 + 1];
                    MMA_FP16(acc[mf][nf], ah[mf], b0, b1);
                    MMA_FP16(acc[mf][nf], al[mf], b0, b1);
                }
        }
        __syncthreads();
    }

#pragma unroll
    for (int mf = 0; mf < 4; mf++) {
        const int r0 = bm + wm + mf * 16 + (lane >> 2);
#pragma unroll
        for (int nf = 0; nf < 4; nf++) {
            const int c = bn + wn + nf * 8 + (lane & 3) * 2;
            const float b0 = bias[c], b1 = bias[c + 1];
            float2 v0 = make_float2(acc[mf][nf][0] + b0, acc[mf][nf][1] + b1);
            float2 v1 = make_float2(acc[mf][nf][2] + b0, acc[mf][nf][3] + b1);
            *(float2*)&Y[(size_t)r0 * DM + c] = v0;
            *(float2*)&Y[(size_t)(r0 + 8) * DM + c] = v1;
        }
    }
}

// ---------------------------------------------------------------------------
// RoPE + fp16 convert: g_q,g_k (fp32) -> g_qh (x0.125, fp16), g_kh (fp16)
// ---------------------------------------------------------------------------
__global__ void rope_half_kernel(const float* __restrict__ q,
                                 const float* __restrict__ k,
                                 __half* __restrict__ qh,
                                 __half* __restrict__ kh)
{
    const int gid = blockIdx.x * blockDim.x + threadIdx.x;
    const int d = gid & 31;
    const int h = (gid >> 5) & (NH - 1);
    const int mt = gid >> 9;
    const int t = mt & (TT - 1);

    const float inv = expf(-0.2878231366242558f * (float)d);
    const float ang = (float)t * inv;
    const float c = cosf(ang);
    const float s = sinf(ang);

    const size_t base = (size_t)mt * DM + h * HD + d;
    float q1 = q[base], q2 = q[base + 32];
    qh[base]      = __float2half(0.125f * (q1 * c - q2 * s));
    qh[base + 32] = __float2half(0.125f * (q2 * c + q1 * s));
    float k1 = k[base], k2 = k[base + 32];
    kh[base]      = __float2half(k1 * c - k2 * s);
    kh[base + 32] = __float2half(k2 * c + k1 * s);
}

// ---------------------------------------------------------------------------
// V transpose + fp16 convert: g_v [b*T+t][h*64+d] -> g_vt [bh][d][t]
// ---------------------------------------------------------------------------
#define FST 72

__global__ __launch_bounds__(256) void v_trans_kernel(
    const float* __restrict__ V, __half* __restrict__ Vt)
{
    __shared__ __half s[64 * FST];
    const int tid = threadIdx.x;
    const int bh = blockIdx.y;
    const int t0 = blockIdx.x * 64;
    const int b = bh >> 4, h = bh & 15;

    {
        const int trow = tid >> 2, dseg = (tid & 3) * 16;
        const float* src = V + ((size_t)(b * TT + t0 + trow)) * DM + h * HD + dseg;
#pragma unroll
        for (int q = 0; q < 4; q++) {
            float4 v4 = ((const float4*)src)[q];
            s[(dseg + q * 4 + 0) * FST + trow] = __float2half(v4.x);
            s[(dseg + q * 4 + 1) * FST + trow] = __float2half(v4.y);
            s[(dseg + q * 4 + 2) * FST + trow] = __float2half(v4.z);
            s[(dseg + q * 4 + 3) * FST + trow] = __float2half(v4.w);
        }
    }
    __syncthreads();
    {
        const int drow = tid >> 2, tseg = (tid & 3) * 16;
        uint4* dst = (uint4*)(Vt + ((size_t)(bh * HD + drow)) * TT + t0 + tseg);
        const uint4* ssrc = (const uint4*)(s + drow * FST + tseg);
        dst[0] = ssrc[0];
        dst[1] = ssrc[1];
    }
}

// ---------------------------------------------------------------------------
// Flash attention, fp16 mma.sync.  grid = (T/128, B*H), 256 threads.
// 8 warps x 16 q-rows. cp.async double-buffered K/V tiles (64 keys).
// B-frags loaded pairwise via ldmatrix.x4.
// ---------------------------------------------------------------------------
#define FLASH_SMEM ((128 * FST + 4 * 64 * FST) * 2)   // 55296 B

__global__ __launch_bounds__(256, 2) void flash_mma_kernel(
    const __half* __restrict__ Qh, const __half* __restrict__ Kh,
    const __half* __restrict__ Vt, float* __restrict__ O)
{
    extern __shared__ __half fsm[];
    __half* Qs = fsm;                       // 128 x FST
    __half* Ks = fsm + 128 * FST;           // 2 x (64 x FST)
    __half* Vs = Ks + 2 * 64 * FST;         // 2 x (64 x FST)

    const int tid = threadIdx.x, wid = tid >> 5, lane = tid & 31;
    const int bh = blockIdx.y;
    const int b = bh >> 4, h = bh & 15;
    const int r0 = blockIdx.x * 128;
    const size_t rowb = (size_t)(b * TT + r0);

    // Q tile -> smem
    {
        const int row = tid >> 1, off = (tid & 1) * 32;
        const uint4* src = (const uint4*)(Qh + (rowb + row) * DM + h * HD + off);
        uint4* dst = (uint4*)(Qs + row * FST + off);
        dst[0] = src[0]; dst[1] = src[1]; dst[2] = src[2]; dst[3] = src[3];
    }

    // cp.async source/dest for K/V tiles
    const int lrow = tid >> 2, lseg = (tid & 3) * 16;
    const __half* ksrc = Kh + ((size_t)(b * TT) + lrow) * DM + h * HD + lseg;
    const __half* vsrc = Vt + ((size_t)(bh * HD + lrow)) * TT + lseg;
    const uint32_t kdst = smem_u32(Ks + lrow * FST + lseg);
    const uint32_t vdst = smem_u32(Vs + lrow * FST + lseg);
    const uint32_t bufB = 64 * FST * 2;

    // ldmatrix bases
    const uint32_t aBase = smem_u32(Qs + (wid * 16 + (lane & 15)) * FST + (lane >> 4) * 8);
    // x4 B-pair base: lanes 0-15 -> rows 0-7 (col halves), lanes 16-31 -> rows 8-15
    const int b4row = ((lane >> 4) << 3) + (lane & 7);
    const int b4col = ((lane >> 3) & 1) * 8;
    const uint32_t kBase = smem_u32(Ks + b4row * FST + b4col);
    const uint32_t vBase = smem_u32(Vs + b4row * FST + b4col);

    float oacc[8][4];
#pragma unroll
    for (int j = 0; j < 8; j++)
#pragma unroll
        for (int r = 0; r < 4; r++) oacc[j][r] = 0.f;
    float m0 = -1e30f, m1 = -1e30f, l0 = 0.f, l1 = 0.f;

    // prologue: tile 0
    CP16(kdst, ksrc);               CP16(kdst + 16, (const char*)ksrc + 16);
    CP16(vdst, vsrc);               CP16(vdst + 16, (const char*)vsrc + 16);
    CPCOMMIT();

    for (int t = 0; t < TT / 64; t++) {
        const int buf = t & 1;
        if (t + 1 < TT / 64) {
            const int c1 = (t + 1) * 64;
            const uint32_t kb = kdst + (buf ^ 1) * bufB;
            const uint32_t vb = vdst + (buf ^ 1) * bufB;
            const __half* kp = ksrc + (size_t)c1 * DM;
            const __half* vp = vsrc + c1;
            CP16(kb, kp);  CP16(kb + 16, (const char*)kp + 16);
            CP16(vb, vp);  CP16(vb + 16, (const char*)vp + 16);
        }
        CPCOMMIT();
        CPWAIT1();
        __syncthreads();

        // ---- S = Qs @ Ks^T (scale pre-folded into Q) ----
        float sacc[8][4];
#pragma unroll
        for (int j = 0; j < 8; j++)
#pragma unroll
            for (int r = 0; r < 4; r++) sacc[j][r] = 0.f;

        const uint32_t kB = kBase + buf * bufB;
#pragma unroll
        for (int s = 0; s < 4; s++) {
            uint32_t a[4];
            LDSM4(a, aBase + s * 32);
#pragma unroll
            for (int j2 = 0; j2 < 4; j2++) {
                uint32_t bk[4];
                LDSM4(bk, kB + s * 32 + j2 * (16 * FST * 2));
                MMA_FP16(sacc[2 * j2],     a, bk[0], bk[1]);
                MMA_FP16(sacc[2 * j2 + 1], a, bk[2], bk[3]);
            }
        }

        // ---- online softmax ----
        float mx0 = -1e30f, mx1 = -1e30f;
#pragma unroll
        for (int j = 0; j < 8; j++) {
            mx0 = fmaxf(mx0, fmaxf(sacc[j][0], sacc[j][1]));
            mx1 = fmaxf(mx1, fmaxf(sacc[j][2], sacc[j][3]));
        }
        mx0 = fmaxf(mx0, __shfl_xor_sync(0xffffffffu, mx0, 1));
        mx0 = fmaxf(mx0, __shfl_xor_sync(0xffffffffu, mx0, 2));
        mx1 = fmaxf(mx1, __shfl_xor_sync(0xffffffffu, mx1, 1));
        mx1 = fmaxf(mx1, __shfl_xor_sync(0xffffffffu, mx1, 2));

        const float mn0 = fmaxf(m0, mx0), mn1 = fmaxf(m1, mx1);
        const float al0 = __expf(m0 - mn0), al1 = __expf(m1 - mn1);
        m0 = mn0; m1 = mn1;

        float sum0 = 0.f, sum1 = 0.f;
        uint32_t P0[8], P1[8];
#pragma unroll
        for (int j = 0; j < 8; j++) {
            float p0 = __expf(sacc[j][0] - m0);
            float p1 = __expf(sacc[j][1] - m0);
            float p2 = __expf(sacc[j][2] - m1);
            float p3 = __expf(sacc[j][3] - m1);
            sum0 += p0 + p1;
            sum1 += p2 + p3;
            __half2 h0 = __floats2half2_rn(p0, p1);
            __half2 h1 = __floats2half2_rn(p2, p3);
            P0[j] = *reinterpret_cast<uint32_t*>(&h0);
            P1[j] = *reinterpret_cast<uint32_t*>(&h1);
        }
        sum0 += __shfl_xor_sync(0xffffffffu, sum0, 1);
        sum0 += __shfl_xor_sync(0xffffffffu, sum0, 2);
        sum1 += __shfl_xor_sync(0xffffffffu, sum1, 1);
        sum1 += __shfl_xor_sync(0xffffffffu, sum1, 2);
        l0 = l0 * al0 + sum0;
        l1 = l1 * al1 + sum1;

#pragma unroll
        for (int j = 0; j < 8; j++) {
            oacc[j][0] *= al0; oacc[j][1] *= al0;
            oacc[j][2] *= al1; oacc[j][3] *= al1;
        }

        // ---- O += P @ V  (A frags from P0/P1 regs) ----
        const uint32_t vB = vBase + buf * bufB;
#pragma unroll
        for (int s = 0; s < 4; s++) {
            uint32_t ap[4];
            ap[0] = P0[2 * s];     ap[1] = P1[2 * s];
            ap[2] = P0[2 * s + 1]; ap[3] = P1[2 * s + 1];
#pragma unroll
            for (int j2 = 0; j2 < 4; j2++) {
                uint32_t bv[4];
                LDSM4(bv, vB + s * 32 + j2 * (16 * FST * 2));
                MMA_FP16(oacc[2 * j2],     ap, bv[0], bv[1]);
                MMA_FP16(oacc[2 * j2 + 1], ap, bv[2], bv[3]);
            }
        }
        __syncthreads();
    }

    // epilogue
    const float inv0 = 1.f / l0, inv1 = 1.f / l1;
    const size_t orow = rowb + wid * 16 + (lane >> 2);
    float* op0 = O + orow * DM + h * HD + (lane & 3) * 2;
    float* op1 = op0 + 8 * DM;
#pragma unroll
    for (int j = 0; j < 8; j++) {
        *(float2*)(op0 + j * 8) = make_float2(oacc[j][0] * inv0, oacc[j][1] * inv0);
        *(float2*)(op1 + j * 8) = make_float2(oacc[j][2] * inv1, oacc[j][3] * inv1);
    }
}

// ---------------------------------------------------------------------------
extern "C" void kernel_launch(void* const* d_in, const int* in_sizes, int n_in,
                              void* d_out, int out_size)
{
    (void)in_sizes; (void)n_in; (void)out_size;
    const float* q_in = (const float*)d_in[0];
    const float* k_in = (const float*)d_in[1];
    const float* v_in = (const float*)d_in[2];
    const float* Wq   = (const float*)d_in[3];
    const float* bq   = (const float*)d_in[4];
    const float* Wk   = (const float*)d_in[5];
    const float* bk   = (const float*)d_in[6];
    const float* Wv   = (const float*)d_in[7];
    const float* bv   = (const float*)d_in[8];
    const float* Wo   = (const float*)d_in[9];
    const float* bo   = (const float*)d_in[10];
    float* out = (float*)d_out;

    float *gq, *gk, *gv, *ga;
    __half *gqh, *gkh, *gvt;
    cudaGetSymbolAddress((void**)&gq, g_q);
    cudaGetSymbolAddress((void**)&gk, g_k);
    cudaGetSymbolAddress((void**)&gv, g_v);
    cudaGetSymbolAddress((void**)&ga, g_a);
    cudaGetSymbolAddress((void**)&gqh, g_qh);
    cudaGetSymbolAddress((void**)&gkh, g_kh);
    cudaGetSymbolAddress((void**)&gvt, g_vt);

    cudaFuncSetAttribute(gemm_mma_kernel,
                         cudaFuncAttributeMaxDynamicSharedMemorySize, GEMM_SMEM);
    cudaFuncSetAttribute(flash_mma_kernel,
                         cudaFuncAttributeMaxDynamicSharedMemorySize, FLASH_SMEM);

    const dim3 ggrid(DM / 128, MM / 128);   // (8, 32)
    gemm_mma_kernel<<<ggrid, 256, GEMM_SMEM>>>(q_in, Wq, bq, gq);
    gemm_mma_kernel<<<ggrid, 256, GEMM_SMEM>>>(k_in, Wk, bk, gk);
    gemm_mma_kernel<<<ggrid, 256, GEMM_SMEM>>>(v_in, Wv, bv, gv);

    rope_half_kernel<<<(MM * NH * 32) / 256, 256>>>(gq, gk, gqh, gkh);
    v_trans_kernel<<<dim3(TT / 64, BB * NH), 256>>>(gv, gvt);

    flash_mma_kernel<<<dim3(TT / 128, BB * NH), 256, FLASH_SMEM>>>(gqh, gkh, gvt, ga);

    gemm_mma_kernel<<<ggrid, 256, GEMM_SMEM>>>(ga, Wo, bo, out);
}